// round 8
// baseline (speedup 1.0000x reference)
#include <cuda_runtime.h>
#include <cstdint>

// PolicyEncoder gather-sum:
// out[n, :] = bias + w_state0[obs0[n]] + w_state1[obs1[n]] + w_act0[act0[n]] + w_act1[act1[n]]
// N = 262144 rows, D = 128 floats per row.
//
// R8: column-sliced blocks with act tables staged in SMEM.
//  - Chip is pinned at the LTS cap (~6300 B/cyc). Act-table gathers are 268MB
//    of the ~670MB/launch L2 traffic; serving them from SMEM removes them.
//  - grid = (16 row-chunks, 8 column slices). Each block owns a 16-float
//    (64B) slice of D for 16384 rows. It preloads the matching slice of BOTH
//    act tables into smem (1000 rows x 16 floats, stride padded to 20 floats
//    for float4 alignment + bank spread; 160KB total -> 1 block/SM, 32 warps).
//  - Main loop: 4 lanes per row (float4 each), 8 consecutive rows per warp,
//    R5-style 2-stage software pipeline on index loads + state gathers.
//    Act lookups are smem reads; output uses streaming stores (__stcs).
//  - Fallback: if act tables don't fit smem (defensive), use the R5 kernel.

// ---------------- sliced kernel ----------------

__global__ void __launch_bounds__(1024, 1)
pe_sliced_kernel(const int* __restrict__ obs0,
                 const int* __restrict__ obs1,
                 const int* __restrict__ act0,
                 const int* __restrict__ act1,
                 const float4* __restrict__ w0,   // [OBS0, 32] state
                 const float4* __restrict__ w1,   // [OBS1, 32] state
                 const float*  __restrict__ w2f,  // [AROWS0, 128] act
                 const float*  __restrict__ w3f,  // [AROWS1, 128] act
                 const float4* __restrict__ bias, // [32]
                 float4* __restrict__ out,        // [N, 32]
                 int n, int aRows0, int aRows1)
{
    extern __shared__ float sm[];
    float* smA = sm;                    // [aRows0 * 20]
    float* smB = sm + (size_t)aRows0 * 20;

    const int slice = blockIdx.y;       // 0..7 (16-float slice of D)

    // ---- preload act-table slices into smem ----
    for (int i = threadIdx.x; i < aRows0 * 16; i += 1024) {
        int r = i >> 4, c = i & 15;
        smA[r * 20 + c] = __ldg(w2f + (size_t)r * 128 + slice * 16 + c);
    }
    for (int i = threadIdx.x; i < aRows1 * 16; i += 1024) {
        int r = i >> 4, c = i & 15;
        smB[r * 20 + c] = __ldg(w3f + (size_t)r * 128 + slice * 16 + c);
    }
    __syncthreads();

    const int warp = threadIdx.x >> 5;  // 0..31
    const int lane = threadIdx.x & 31;
    const int rsub = lane >> 2;         // row within warp group (0..7)
    const int c    = lane & 3;          // float4 column within slice (0..3)

    const int rowsPerBlock = (n + gridDim.x - 1) / gridDim.x;
    const int r0   = blockIdx.x * rowsPerBlock;
    int rEnd = r0 + rowsPerBlock; if (rEnd > n) rEnd = n;

    const int rFirst = r0 + warp * 8 + rsub;
    if (rFirst >= rEnd) return;
    const int last = rEnd - 1;
    const int step = 256;               // 32 warps * 8 rows

    const float4 b = __ldg(bias + slice * 4 + c);
    const int f4off = slice * 4 + c;    // float4 offset within a 32-float4 row

    // ---- prologue ----
    int i0 = __ldg(obs0 + rFirst);
    int i1 = __ldg(obs1 + rFirst);
    int j2 = __ldg(act0 + rFirst);
    int j3 = __ldg(act1 + rFirst);

    int rn = rFirst + step; rn = rn <= last ? rn : last;
    int n0 = __ldg(obs0 + rn);
    int n1 = __ldg(obs1 + rn);
    int n2 = __ldg(act0 + rn);
    int n3 = __ldg(act1 + rn);

    float4 g0 = __ldg(w0 + (size_t)i0 * 32 + f4off);
    float4 g1 = __ldg(w1 + (size_t)i1 * 32 + f4off);

    // ---- steady state ----
    for (int r = rFirst; r <= last; r += step) {
        // indices for r + 2*step (clamped at tail)
        int rnn = r + 2 * step; rnn = rnn <= last ? rnn : last;
        int m0 = __ldg(obs0 + rnn);
        int m1 = __ldg(obs1 + rnn);
        int m2 = __ldg(act0 + rnn);
        int m3 = __ldg(act1 + rnn);

        // state gathers for r + step (indices arrived last iteration)
        float4 h0 = __ldg(w0 + (size_t)n0 * 32 + f4off);
        float4 h1 = __ldg(w1 + (size_t)n1 * 32 + f4off);

        // act lookups for current row from smem (cheap, 29cyc)
        const float4 a2 = *(const float4*)(smA + (size_t)j2 * 20 + c * 4);
        const float4 a3 = *(const float4*)(smB + (size_t)j3 * 20 + c * 4);

        float4 res;
        res.x = b.x + g0.x + g1.x + a2.x + a3.x;
        res.y = b.y + g0.y + g1.y + a2.y + a3.y;
        res.z = b.z + g0.z + g1.z + a2.z + a3.z;
        res.w = b.w + g0.w + g1.w + a2.w + a3.w;
        __stcs(out + (size_t)r * 32 + f4off, res);

        // rotate pipeline
        g0 = h0; g1 = h1;
        j2 = n2; j3 = n3;
        n0 = m0; n1 = m1; n2 = m2; n3 = m3;
    }
}

// ---------------- fallback (R5): persistent warp-per-row pipeline ----------------

struct Idx { int i0, i1, i2, i3; };

__device__ __forceinline__ Idx load_idx4(const int* __restrict__ o0,
                                         const int* __restrict__ o1,
                                         const int* __restrict__ a0,
                                         const int* __restrict__ a1, int r) {
    Idx x;
    x.i0 = __ldg(o0 + r); x.i1 = __ldg(o1 + r);
    x.i2 = __ldg(a0 + r); x.i3 = __ldg(a1 + r);
    return x;
}

__global__ void __launch_bounds__(256, 4)
pe_fallback_kernel(const int* __restrict__ obs0, const int* __restrict__ obs1,
                   const int* __restrict__ act0, const int* __restrict__ act1,
                   const float4* __restrict__ w0, const float4* __restrict__ w1,
                   const float4* __restrict__ w2, const float4* __restrict__ w3,
                   const float4* __restrict__ bias, float4* __restrict__ out, int n)
{
    const int lane   = threadIdx.x & 31;
    const int gw     = (int)((blockIdx.x * blockDim.x + threadIdx.x) >> 5);
    const int stride = (int)((gridDim.x * blockDim.x) >> 5);
    if (gw >= n) return;

    const float4 b = __ldg(bias + lane);
    const int last = n - 1;

    Idx ic = load_idx4(obs0, obs1, act0, act1, gw);
    int r1 = gw + stride;
    Idx in_ = load_idx4(obs0, obs1, act0, act1, r1 <= last ? r1 : last);

    float4 g0 = __ldg(w0 + (size_t)ic.i0 * 32 + lane);
    float4 g1 = __ldg(w1 + (size_t)ic.i1 * 32 + lane);
    float4 g2 = __ldg(w2 + (size_t)ic.i2 * 32 + lane);
    float4 g3 = __ldg(w3 + (size_t)ic.i3 * 32 + lane);

    for (int r = gw; r <= last; r += stride) {
        int rnn = r + 2 * stride;
        Idx inn = load_idx4(obs0, obs1, act0, act1, rnn <= last ? rnn : last);

        float4 h0 = __ldg(w0 + (size_t)in_.i0 * 32 + lane);
        float4 h1 = __ldg(w1 + (size_t)in_.i1 * 32 + lane);
        float4 h2 = __ldg(w2 + (size_t)in_.i2 * 32 + lane);
        float4 h3 = __ldg(w3 + (size_t)in_.i3 * 32 + lane);

        float4 res;
        res.x = b.x + g0.x + g1.x + g2.x + g3.x;
        res.y = b.y + g0.y + g1.y + g2.y + g3.y;
        res.z = b.z + g0.z + g1.z + g2.z + g3.z;
        res.w = b.w + g0.w + g1.w + g2.w + g3.w;
        __stcs(out + (size_t)r * 32 + lane, res);

        g0 = h0; g1 = h1; g2 = h2; g3 = h3;
        in_ = inn;
    }
}

extern "C" void kernel_launch(void* const* d_in, const int* in_sizes, int n_in,
                              void* d_out, int out_size)
{
    const int*    obs0 = (const int*)d_in[0];
    const int*    obs1 = (const int*)d_in[1];
    const int*    act0 = (const int*)d_in[2];
    const int*    act1 = (const int*)d_in[3];
    const float4* w0   = (const float4*)d_in[4];
    const float4* w1   = (const float4*)d_in[5];
    const float*  w2f  = (const float*)d_in[6];
    const float*  w3f  = (const float*)d_in[7];
    const float4* bias = (const float4*)d_in[8];
    float4*       out  = (float4*)d_out;

    const int n      = in_sizes[0];
    const int D      = in_sizes[8];          // 128
    const int aRows0 = in_sizes[6] / D;      // act table rows
    const int aRows1 = in_sizes[7] / D;

    const size_t smemBytes = ((size_t)aRows0 + aRows1) * 20 * sizeof(float);

    if (D == 128 && smemBytes <= 200000) {
        cudaFuncSetAttribute(pe_sliced_kernel,
                             cudaFuncAttributeMaxDynamicSharedMemorySize,
                             (int)smemBytes);
        dim3 grid(16, 8);                    // 16 row-chunks x 8 column slices
        pe_sliced_kernel<<<grid, 1024, smemBytes>>>(
            obs0, obs1, act0, act1, w0, w1, w2f, w3f, bias, out,
            n, aRows0, aRows1);
    } else {
        const int threads = 256;
        const int blocks  = 148 * 4;
        pe_fallback_kernel<<<blocks, threads>>>(
            obs0, obs1, act0, act1, w0, w1,
            (const float4*)w2f, (const float4*)w3f, bias, out, n);
    }
}

// round 9
// speedup vs baseline: 1.3076x; 1.3076x over previous
#include <cuda_runtime.h>
#include <cstdint>

// PolicyEncoder gather-sum:
// out[n, :] = bias + w_state0[obs0[n]] + w_state1[obs1[n]] + w_act0[act0[n]] + w_act1[act1[n]]
// N = 262144 rows, D = 128 floats per row.
//
// R9: 4-way column slice (32 floats = 128B = one L2 line per gather).
//  - grid (37,4) = 148 blocks = one block per SM. 1024 threads, 144KB smem.
//  - act0 slice lives in smem (1000 x 36 floats, pad -> conflict-free LDS).
//  - act1 slice (128KB working set) served by L1: state gathers use __ldcg
//    (L2-only) so they don't evict it.
//  - Per warp: 4 rows x 8 lanes (16B each). 2-stage pipeline on index loads,
//    state gathers and act1 gathers. Streaming stores.
//  - Fallback to the R5 persistent-pipeline kernel for unexpected shapes.

__global__ void __launch_bounds__(1024, 1)
pe_slice4_kernel(const int* __restrict__ obs0,
                 const int* __restrict__ obs1,
                 const int* __restrict__ act0,
                 const int* __restrict__ act1,
                 const float4* __restrict__ w0,   // [OBS0, 32] state (L2-only)
                 const float4* __restrict__ w1,   // [OBS1, 32] state (L2-only)
                 const float*  __restrict__ w2f,  // [AROWS0, 128] act0 -> smem
                 const float4* __restrict__ w3,   // [AROWS1, 32] act1 -> L1
                 const float4* __restrict__ bias, // [32]
                 float4* __restrict__ out,        // [N, 32]
                 int n, int aRows0, int rowsPerChunk)
{
    extern __shared__ float smA[];       // [aRows0][36]

    const int slice = blockIdx.y;        // 0..3, owns floats [slice*32, slice*32+32)

    // ---- preload act0 slice into smem (coalesced 128B reads) ----
    const int nElems = aRows0 * 32;
    for (int idx = threadIdx.x; idx < nElems; idx += 1024) {
        int j = idx >> 5, c = idx & 31;
        smA[j * 36 + c] = __ldg(w2f + (size_t)j * 128 + slice * 32 + c);
    }
    __syncthreads();

    const int warp = threadIdx.x >> 5;   // 0..31
    const int lane = threadIdx.x & 31;
    const int rsub = lane >> 3;          // 0..3 : row within warp
    const int c    = lane & 7;           // 0..7 : float4 within 128B slice

    const int r0 = blockIdx.x * rowsPerChunk;
    int rEnd = r0 + rowsPerChunk; if (rEnd > n) rEnd = n;
    const int rFirst = r0 + warp * 4 + rsub;
    if (rFirst >= rEnd) return;
    const int last = rEnd - 1;
    const int step = 128;                // 32 warps * 4 rows

    const int f4off = slice * 8 + c;     // float4 index within the 32-f4 row
    const float4 b  = __ldg(bias + f4off);

    // ---- prologue ----
    int jA;                              // act0 idx for current row
    float4 g0, g1, a1;                   // state + act1 for current row
    {
        const int i0 = __ldg(obs0 + rFirst);
        const int i1 = __ldg(obs1 + rFirst);
        jA           = __ldg(act0 + rFirst);
        const int i3 = __ldg(act1 + rFirst);
        g0 = __ldcg(w0 + (size_t)i0 * 32 + f4off);
        g1 = __ldcg(w1 + (size_t)i1 * 32 + f4off);
        a1 = __ldg (w3 + (size_t)i3 * 32 + f4off);
    }
    int rn = rFirst + step; rn = rn <= last ? rn : last;
    int n0 = __ldg(obs0 + rn);
    int n1 = __ldg(obs1 + rn);
    int n2 = __ldg(act0 + rn);
    int n3 = __ldg(act1 + rn);

    // ---- steady state ----
    for (int r = rFirst; r <= last; r += step) {
        // indices for r + 2*step (clamped at tail)
        int rnn = r + 2 * step; rnn = rnn <= last ? rnn : last;
        const int m0 = __ldg(obs0 + rnn);
        const int m1 = __ldg(obs1 + rnn);
        const int m2 = __ldg(act0 + rnn);
        const int m3 = __ldg(act1 + rnn);

        // gathers for r + step (indices arrived last iteration)
        const float4 h0 = __ldcg(w0 + (size_t)n0 * 32 + f4off);
        const float4 h1 = __ldcg(w1 + (size_t)n1 * 32 + f4off);
        const float4 h3 = __ldg (w3 + (size_t)n3 * 32 + f4off);

        // act0 for current row from smem (conflict-free: stride 36)
        const float4 a0 = *(const float4*)(smA + (size_t)jA * 36 + c * 4);

        float4 res;
        res.x = b.x + g0.x + g1.x + a0.x + a1.x;
        res.y = b.y + g0.y + g1.y + a0.y + a1.y;
        res.z = b.z + g0.z + g1.z + a0.z + a1.z;
        res.w = b.w + g0.w + g1.w + a0.w + a1.w;
        __stcs(out + (size_t)r * 32 + f4off, res);

        // rotate pipeline
        g0 = h0; g1 = h1; a1 = h3; jA = n2;
        n0 = m0; n1 = m1; n2 = m2; n3 = m3;
    }
}

// ---------------- fallback (R5): persistent warp-per-row pipeline ----------------

struct Idx { int i0, i1, i2, i3; };

__device__ __forceinline__ Idx load_idx4(const int* __restrict__ o0,
                                         const int* __restrict__ o1,
                                         const int* __restrict__ a0,
                                         const int* __restrict__ a1, int r) {
    Idx x;
    x.i0 = __ldg(o0 + r); x.i1 = __ldg(o1 + r);
    x.i2 = __ldg(a0 + r); x.i3 = __ldg(a1 + r);
    return x;
}

__global__ void __launch_bounds__(256, 4)
pe_fallback_kernel(const int* __restrict__ obs0, const int* __restrict__ obs1,
                   const int* __restrict__ act0, const int* __restrict__ act1,
                   const float4* __restrict__ w0, const float4* __restrict__ w1,
                   const float4* __restrict__ w2, const float4* __restrict__ w3,
                   const float4* __restrict__ bias, float4* __restrict__ out, int n)
{
    const int lane   = threadIdx.x & 31;
    const int gw     = (int)((blockIdx.x * blockDim.x + threadIdx.x) >> 5);
    const int stride = (int)((gridDim.x * blockDim.x) >> 5);
    if (gw >= n) return;

    const float4 b = __ldg(bias + lane);
    const int last = n - 1;

    Idx ic = load_idx4(obs0, obs1, act0, act1, gw);
    int r1 = gw + stride;
    Idx in_ = load_idx4(obs0, obs1, act0, act1, r1 <= last ? r1 : last);

    float4 g0 = __ldg(w0 + (size_t)ic.i0 * 32 + lane);
    float4 g1 = __ldg(w1 + (size_t)ic.i1 * 32 + lane);
    float4 g2 = __ldg(w2 + (size_t)ic.i2 * 32 + lane);
    float4 g3 = __ldg(w3 + (size_t)ic.i3 * 32 + lane);

    for (int r = gw; r <= last; r += stride) {
        int rnn = r + 2 * stride;
        Idx inn = load_idx4(obs0, obs1, act0, act1, rnn <= last ? rnn : last);

        float4 h0 = __ldg(w0 + (size_t)in_.i0 * 32 + lane);
        float4 h1 = __ldg(w1 + (size_t)in_.i1 * 32 + lane);
        float4 h2 = __ldg(w2 + (size_t)in_.i2 * 32 + lane);
        float4 h3 = __ldg(w3 + (size_t)in_.i3 * 32 + lane);

        float4 res;
        res.x = b.x + g0.x + g1.x + g2.x + g3.x;
        res.y = b.y + g0.y + g1.y + g2.y + g3.y;
        res.z = b.z + g0.z + g1.z + g2.z + g3.z;
        res.w = b.w + g0.w + g1.w + g2.w + g3.w;
        __stcs(out + (size_t)r * 32 + lane, res);

        g0 = h0; g1 = h1; g2 = h2; g3 = h3;
        in_ = inn;
    }
}

extern "C" void kernel_launch(void* const* d_in, const int* in_sizes, int n_in,
                              void* d_out, int out_size)
{
    const int*    obs0 = (const int*)d_in[0];
    const int*    obs1 = (const int*)d_in[1];
    const int*    act0 = (const int*)d_in[2];
    const int*    act1 = (const int*)d_in[3];
    const float4* w0   = (const float4*)d_in[4];
    const float4* w1   = (const float4*)d_in[5];
    const float*  w2f  = (const float*)d_in[6];
    const float4* w3   = (const float4*)d_in[7];
    const float4* bias = (const float4*)d_in[8];
    float4*       out  = (float4*)d_out;

    const int n      = in_sizes[0];
    const int D      = in_sizes[8];          // 128
    const int aRows0 = in_sizes[6] / (D > 0 ? D : 1);

    const size_t smemBytes = (size_t)aRows0 * 36 * sizeof(float);  // 144KB @1000

    if (D == 128 && smemBytes <= 160000) {
        cudaFuncSetAttribute(pe_slice4_kernel,
                             cudaFuncAttributeMaxDynamicSharedMemorySize,
                             (int)smemBytes);
        const int chunks = 37;               // 37 * 4 slices = 148 blocks
        const int rowsPerChunk = (n + chunks - 1) / chunks;
        dim3 grid(chunks, 4);
        pe_slice4_kernel<<<grid, 1024, smemBytes>>>(
            obs0, obs1, act0, act1, w0, w1, w2f, w3, bias, out,
            n, aRows0, rowsPerChunk);
    } else {
        const int threads = 256;
        const int blocks  = 148 * 4;
        pe_fallback_kernel<<<blocks, threads>>>(
            obs0, obs1, act0, act1, w0, w1,
            (const float4*)w2f, w3, bias, out, n);
    }
}

// round 10
// speedup vs baseline: 1.3250x; 1.0133x over previous
#include <cuda_runtime.h>
#include <cstdint>

// PolicyEncoder gather-sum:
// out[n, :] = bias + w_state0[obs0[n]] + w_state1[obs1[n]] + w_act0[act0[n]] + w_act1[act1[n]]
// N = 262144 rows, D = 128 floats per row.
//
// R10 = R5 structure (warp-per-row, 2-stage gather pipeline, 148*4 blocks,
// streaming stores) + warp-cooperative index loading:
//  - Each warp owns a CONTIGUOUS chunk of ~56 rows. Indices are loaded in
//    32-row tiles with 4 coalesced LDG.32 per tile (obs0/obs1/act0/act1
//    at tileBase+lane), then distributed per-row via __shfl_sync (ALU pipe).
//    This removes 4 broadcast index LDGs per row from the LSU/L1tex path.
//  - Index tiles are double-buffered so the gather pipeline never bubbles
//    at tile boundaries.
//  - Gathers stay __ldg (L1 allowed: act tables get hits), output __stcs.

__global__ void __launch_bounds__(256, 4)
policy_encoder_kernel(const int* __restrict__ obs0,
                      const int* __restrict__ obs1,
                      const int* __restrict__ act0,
                      const int* __restrict__ act1,
                      const float4* __restrict__ w0,   // [OBS0, 32] as float4
                      const float4* __restrict__ w1,
                      const float4* __restrict__ w2,
                      const float4* __restrict__ w3,
                      const float4* __restrict__ bias, // [32]
                      float4* __restrict__ out,        // [N, 32]
                      int n, int rowsPerWarp)
{
    const int lane = threadIdx.x & 31;
    const int gw   = (int)((blockIdx.x * blockDim.x + threadIdx.x) >> 5);

    const int chunkStart = gw * rowsPerWarp;
    if (chunkStart >= n) return;
    int chunkEnd = chunkStart + rowsPerWarp;
    if (chunkEnd > n) chunkEnd = n;
    const int lastRow = n - 1;

    const float4 b = __ldg(bias + lane);

    // ---- index tile double buffer ----
    // cur tile covers [tb, tb+32), next tile [tb+32, tb+64); loads clamped.
    int tb = chunkStart;
    int rc = tb + lane;        rc = rc <= lastRow ? rc : lastRow;
    int c0 = __ldg(obs0 + rc), c1 = __ldg(obs1 + rc);
    int c2 = __ldg(act0 + rc), c3 = __ldg(act1 + rc);

    int rn = tb + 32 + lane;   rn = rn <= lastRow ? rn : lastRow;
    int x0 = __ldg(obs0 + rn), x1 = __ldg(obs1 + rn);
    int x2 = __ldg(act0 + rn), x3 = __ldg(act1 + rn);

    // ---- prime gather pipeline with row tb (indices from cur tile, lane 0) ----
    int i0 = __shfl_sync(0xffffffffu, c0, 0);
    int i1 = __shfl_sync(0xffffffffu, c1, 0);
    int i2 = __shfl_sync(0xffffffffu, c2, 0);
    int i3 = __shfl_sync(0xffffffffu, c3, 0);
    float4 g0 = __ldg(w0 + (size_t)i0 * 32 + lane);
    float4 g1 = __ldg(w1 + (size_t)i1 * 32 + lane);
    float4 g2 = __ldg(w2 + (size_t)i2 * 32 + lane);
    float4 g3 = __ldg(w3 + (size_t)i3 * 32 + lane);

    // ---- tile loop ----
    for (; tb < chunkEnd; tb += 32) {
        const int tLen = (chunkEnd - tb) < 32 ? (chunkEnd - tb) : 32;
        const bool hasNextTile = (tb + 32) < chunkEnd;

        for (int k = 0; k < tLen; ++k) {
            // indices for the NEXT row (pipeline stage 2)
            int j0, j1, j2, j3;
            if (k + 1 < tLen) {
                j0 = __shfl_sync(0xffffffffu, c0, k + 1);
                j1 = __shfl_sync(0xffffffffu, c1, k + 1);
                j2 = __shfl_sync(0xffffffffu, c2, k + 1);
                j3 = __shfl_sync(0xffffffffu, c3, k + 1);
            } else {
                // first row of next tile (clamped values are always valid rows)
                j0 = __shfl_sync(0xffffffffu, x0, 0);
                j1 = __shfl_sync(0xffffffffu, x1, 0);
                j2 = __shfl_sync(0xffffffffu, x2, 0);
                j3 = __shfl_sync(0xffffffffu, x3, 0);
            }

            // issue next row's gathers
            float4 h0 = __ldg(w0 + (size_t)j0 * 32 + lane);
            float4 h1 = __ldg(w1 + (size_t)j1 * 32 + lane);
            float4 h2 = __ldg(w2 + (size_t)j2 * 32 + lane);
            float4 h3 = __ldg(w3 + (size_t)j3 * 32 + lane);

            // consume current row (its gathers were issued last iteration)
            float4 res;
            res.x = b.x + g0.x + g1.x + g2.x + g3.x;
            res.y = b.y + g0.y + g1.y + g2.y + g3.y;
            res.z = b.z + g0.z + g1.z + g2.z + g3.z;
            res.w = b.w + g0.w + g1.w + g2.w + g3.w;
            __stcs(out + (size_t)(tb + k) * 32 + lane, res);

            g0 = h0; g1 = h1; g2 = h2; g3 = h3;
        }

        // rotate index tiles; prefetch tile tb+64
        c0 = x0; c1 = x1; c2 = x2; c3 = x3;
        if (hasNextTile) {
            int rf = tb + 64 + lane;  rf = rf <= lastRow ? rf : lastRow;
            x0 = __ldg(obs0 + rf); x1 = __ldg(obs1 + rf);
            x2 = __ldg(act0 + rf); x3 = __ldg(act1 + rf);
        }
    }
}

extern "C" void kernel_launch(void* const* d_in, const int* in_sizes, int n_in,
                              void* d_out, int out_size)
{
    const int*    obs0 = (const int*)d_in[0];
    const int*    obs1 = (const int*)d_in[1];
    const int*    act0 = (const int*)d_in[2];
    const int*    act1 = (const int*)d_in[3];
    const float4* w0   = (const float4*)d_in[4];
    const float4* w1   = (const float4*)d_in[5];
    const float4* w2   = (const float4*)d_in[6];
    const float4* w3   = (const float4*)d_in[7];
    const float4* bias = (const float4*)d_in[8];
    float4*       out  = (float4*)d_out;

    const int n = in_sizes[0];         // number of rows (N)
    const int threads = 256;           // 8 warps/block
    const int blocks  = 148 * 4;       // one exact wave at 4 blocks/SM
    const int totalWarps = blocks * (threads / 32);           // 4736
    const int rowsPerWarp = (n + totalWarps - 1) / totalWarps; // 56 for N=262144

    policy_encoder_kernel<<<blocks, threads>>>(obs0, obs1, act0, act1,
                                               w0, w1, w2, w3, bias, out,
                                               n, rowsPerWarp);
}

// round 11
// speedup vs baseline: 1.4896x; 1.1242x over previous
#include <cuda_runtime.h>
#include <cstdint>

// PolicyEncoder gather-sum:
// out[n, :] = bias + w_state0[obs0[n]] + w_state1[obs1[n]] + w_act0[act0[n]] + w_act1[act1[n]]
// N = 262144 rows, D = 128 floats per row.
//
// R11 = R5 (best kernel: persistent warps, 2-stage gather pipeline,
// 148*4-block exact wave) with ONE change:
//   output stores use __stwt (st.global.wt, write-through, NO L2 allocation)
//   instead of __stcs. The 134MB/launch output stream was write-allocating
//   in L2 and evicting the ~72MB table working set every launch (~65MB of
//   avoidable DRAM read misses). Write-through keeps L2 for the tables.

struct Idx { int i0, i1, i2, i3; };

__device__ __forceinline__ Idx load_idx(const int* __restrict__ o0,
                                        const int* __restrict__ o1,
                                        const int* __restrict__ a0,
                                        const int* __restrict__ a1, int r) {
    Idx x;
    x.i0 = __ldg(o0 + r);
    x.i1 = __ldg(o1 + r);
    x.i2 = __ldg(a0 + r);
    x.i3 = __ldg(a1 + r);
    return x;
}

__global__ void __launch_bounds__(256, 4)
policy_encoder_kernel(const int* __restrict__ obs0,
                      const int* __restrict__ obs1,
                      const int* __restrict__ act0,
                      const int* __restrict__ act1,
                      const float4* __restrict__ w0,   // [OBS0, 32] as float4
                      const float4* __restrict__ w1,
                      const float4* __restrict__ w2,
                      const float4* __restrict__ w3,
                      const float4* __restrict__ bias, // [32]
                      float4* __restrict__ out,        // [N, 32]
                      int n)
{
    const int lane   = threadIdx.x & 31;
    const int gw     = (int)((blockIdx.x * blockDim.x + threadIdx.x) >> 5);
    const int stride = (int)((gridDim.x * blockDim.x) >> 5);

    if (gw >= n) return;

    const float4 b = __ldg(bias + lane);
    const int last = n - 1;

    // ---- prologue: row0 indices + gathers, row1 indices ----
    Idx ic = load_idx(obs0, obs1, act0, act1, gw);
    int r1 = gw + stride;
    Idx in_ = load_idx(obs0, obs1, act0, act1, r1 <= last ? r1 : last);

    float4 g0 = __ldg(w0 + (size_t)ic.i0 * 32 + lane);
    float4 g1 = __ldg(w1 + (size_t)ic.i1 * 32 + lane);
    float4 g2 = __ldg(w2 + (size_t)ic.i2 * 32 + lane);
    float4 g3 = __ldg(w3 + (size_t)ic.i3 * 32 + lane);

    // ---- steady state ----
    for (int r = gw; r <= last; r += stride) {
        // indices for row r + 2*stride (clamped at tail)
        int rnn = r + 2 * stride;
        Idx inn = load_idx(obs0, obs1, act0, act1, rnn <= last ? rnn : last);

        // gathers for row r + stride (indices arrived last iteration)
        float4 h0 = __ldg(w0 + (size_t)in_.i0 * 32 + lane);
        float4 h1 = __ldg(w1 + (size_t)in_.i1 * 32 + lane);
        float4 h2 = __ldg(w2 + (size_t)in_.i2 * 32 + lane);
        float4 h3 = __ldg(w3 + (size_t)in_.i3 * 32 + lane);

        // consume row r (gathers issued one iteration ago)
        float4 res;
        res.x = b.x + g0.x + g1.x + g2.x + g3.x;
        res.y = b.y + g0.y + g1.y + g2.y + g3.y;
        res.z = b.z + g0.z + g1.z + g2.z + g3.z;
        res.w = b.w + g0.w + g1.w + g2.w + g3.w;
        __stwt(out + (size_t)r * 32 + lane, res);   // write-through, no L2 alloc

        // rotate pipeline registers
        g0 = h0; g1 = h1; g2 = h2; g3 = h3;
        in_ = inn;
    }
}

extern "C" void kernel_launch(void* const* d_in, const int* in_sizes, int n_in,
                              void* d_out, int out_size)
{
    const int*    obs0 = (const int*)d_in[0];
    const int*    obs1 = (const int*)d_in[1];
    const int*    act0 = (const int*)d_in[2];
    const int*    act1 = (const int*)d_in[3];
    const float4* w0   = (const float4*)d_in[4];
    const float4* w1   = (const float4*)d_in[5];
    const float4* w2   = (const float4*)d_in[6];
    const float4* w3   = (const float4*)d_in[7];
    const float4* bias = (const float4*)d_in[8];
    float4*       out  = (float4*)d_out;

    const int n = in_sizes[0];     // number of rows (N)
    const int threads = 256;       // 8 warps/block
    const int blocks  = 148 * 4;   // one exact wave at 4 blocks/SM

    policy_encoder_kernel<<<blocks, threads>>>(obs0, obs1, act0, act1,
                                               w0, w1, w2, w3, bias, out, n);
}